// round 7
// baseline (speedup 1.0000x reference)
#include <cuda_runtime.h>
#include <cfloat>

// Batched Chamfer loss via uniform-grid exact nearest neighbor.
// B=16, N=M=4096, 3D Gaussian points.
// Grid: G^3 cells of size H over [X0, X0+G*H]^3. Expanding-shell search:
// after scanning Chebyshev shells 0..s, all unscanned points are >= s*H away,
// so stop when best d^2 <= (s*H)^2 (with small safety margin).
// Per-pair math identical to brute force: d^2 = q2 + fma(qx,-2tx, fma(qy,-2ty,
// fma(qz,-2tz, |t|^2))), clamped >= 0. Min over a set is order-independent ->
// deterministic despite atomic scatter order.

constexpr int   B_    = 16;
constexpr int   N_    = 4096;
constexpr int   G     = 30;
constexpr int   CELLS = G * G * G;          // 27000
constexpr float H     = 0.35f;
constexpr float X0    = -5.25f;             // G*H = 10.5
constexpr float INVH  = 1.0f / H;

constexpr int QBS     = 256;
constexpr int QCHUNKS = N_ / QBS;           // 16
constexpr int NPART   = 2 * B_ * QCHUNKS;   // 512

constexpr int NPTS_ALL = 2 * B_ * N_;       // 131072

__device__ float4 g_binned[2 * B_ * N_];          // folded: (-2x,-2y,-2z,|t|^2)
__device__ int    g_starts[2 * B_ * (CELLS + 1)];
__device__ int    g_cnt[2 * B_ * CELLS];
__device__ float  g_partial[NPART];

__device__ __forceinline__ int cell_of(float v) {
    int c = (int)floorf((v - X0) * INVH);
    return min(max(c, 0), G - 1);
}

// ---------------- binning passes ----------------

__global__ void zero_cnt_kernel() {
    int i = blockIdx.x * blockDim.x + threadIdx.x;
    if (i < 2 * B_ * CELLS) g_cnt[i] = 0;
}

__global__ void count_kernel(const float* __restrict__ src,
                             const float* __restrict__ tgt) {
    int id = blockIdx.x * blockDim.x + threadIdx.x;   // [0, 131072)
    if (id >= NPTS_ALL) return;
    const int set = id >> 16;                          // B_*N_ = 65536
    const int rem = id & 65535;
    const float* p = (set == 0 ? src : tgt) + (size_t)rem * 3;
    const int c = (cell_of(p[2]) * G + cell_of(p[1])) * G + cell_of(p[0]);
    const int b = rem >> 12;
    atomicAdd(&g_cnt[(set * B_ + b) * CELLS + c], 1);
}

__global__ void __launch_bounds__(1024)
scan_kernel() {                                        // one block per (set,b)
    const int sb = blockIdx.x;                         // 0..31
    const int* cnt = g_cnt + sb * CELLS;
    int* starts = g_starts + sb * (CELLS + 1);
    const int t = threadIdx.x;
    const int base = t * 27;                           // 1024*27 = 27648 >= 27000

    int sum = 0;
#pragma unroll
    for (int i = 0; i < 27; ++i) {
        const int c = base + i;
        if (c < CELLS) sum += cnt[c];
    }
    __shared__ int sh[1024];
    sh[t] = sum;
    __syncthreads();
    for (int d = 1; d < 1024; d <<= 1) {               // Hillis-Steele inclusive
        int v = (t >= d) ? sh[t - d] : 0;
        __syncthreads();
        sh[t] += v;
        __syncthreads();
    }
    int run = sh[t] - sum;                             // exclusive offset
#pragma unroll
    for (int i = 0; i < 27; ++i) {
        const int c = base + i;
        if (c < CELLS) { starts[c] = run; run += cnt[c]; }
    }
    if (t == 1023) starts[CELLS] = sh[1023];           // == 4096
}

__global__ void scatter_kernel(const float* __restrict__ src,
                               const float* __restrict__ tgt) {
    int id = blockIdx.x * blockDim.x + threadIdx.x;
    if (id >= NPTS_ALL) return;
    const int set = id >> 16;
    const int rem = id & 65535;
    const float* p = (set == 0 ? src : tgt) + (size_t)rem * 3;
    const float x = p[0], y = p[1], z = p[2];
    const int c = (cell_of(z) * G + cell_of(y)) * G + cell_of(x);
    const int b = rem >> 12;
    const int sb = set * B_ + b;
    const int pos = g_starts[sb * (CELLS + 1) + c] +
                    atomicAdd(&g_cnt[sb * CELLS + c], 1);
    g_binned[sb * N_ + pos] = make_float4(-2.0f * x, -2.0f * y, -2.0f * z,
                                          x * x + y * y + z * z);
}

// ---------------- query: exact NN via expanding shells ----------------

__global__ void __launch_bounds__(QBS)
query_kernel(const float* __restrict__ src, const float* __restrict__ tgt)
{
    const int dir = blockIdx.z;            // 0: src->tgt (db=tgt), 1: tgt->src
    const int b   = blockIdx.y;
    const int tid = threadIdx.x;
    const int n   = blockIdx.x * QBS + tid;

    const float* qp = (dir == 0 ? src : tgt) + ((size_t)b * N_ + n) * 3;
    const float qx = qp[0], qy = qp[1], qz = qp[2];
    const float q2 = qx * qx + qy * qy + qz * qz;

    const int dbset = dir == 0 ? 1 : 0;
    const int sb = dbset * B_ + b;
    const float4* __restrict__ pts  = g_binned + sb * N_;
    const int*    __restrict__ starts = g_starts + sb * (CELLS + 1);

    const int cx = cell_of(qx), cy = cell_of(qy), cz = cell_of(qz);

    float dbest = FLT_MAX;                 // folded (= d^2 - q2)
    for (int s = 0; s < G; ++s) {
        for (int dz = -s; dz <= s; ++dz) {
            const int z = cz + dz;
            if ((unsigned)z >= (unsigned)G) continue;
            const bool face_z = (dz == -s) | (dz == s);
            for (int dy = -s; dy <= s; ++dy) {
                const int y = cy + dy;
                if ((unsigned)y >= (unsigned)G) continue;
                const int rowBase = (z * G + y) * G;
                if (face_z | (dy == -s) | (dy == s)) {
                    // full x-run: contiguous cells -> contiguous points
                    const int xlo = max(cx - s, 0), xhi = min(cx + s, G - 1);
                    const int p1 = starts[rowBase + xhi + 1];
                    for (int p = starts[rowBase + xlo]; p < p1; ++p) {
                        const float4 t = pts[p];
                        dbest = fminf(dbest,
                                fmaf(qx, t.x, fmaf(qy, t.y, fmaf(qz, t.z, t.w))));
                    }
                } else {
                    // only x = cx-s and cx+s
                    int x = cx - s;
                    if (x >= 0) {
                        const int p1 = starts[rowBase + x + 1];
                        for (int p = starts[rowBase + x]; p < p1; ++p) {
                            const float4 t = pts[p];
                            dbest = fminf(dbest,
                                    fmaf(qx, t.x, fmaf(qy, t.y, fmaf(qz, t.z, t.w))));
                        }
                    }
                    x = cx + s;
                    if (x < G) {
                        const int p1 = starts[rowBase + x + 1];
                        for (int p = starts[rowBase + x]; p < p1; ++p) {
                            const float4 t = pts[p];
                            dbest = fminf(dbest,
                                    fmaf(qx, t.x, fmaf(qy, t.y, fmaf(qz, t.z, t.w))));
                        }
                    }
                }
            }
        }
        // After shells 0..s, unscanned points are >= s*H away (safety margin).
        const float sh_ = (float)s * H;
        if (q2 + dbest <= sh_ * sh_ - 1e-4f) break;
    }

    const float res = fmaxf(q2 + dbest, 0.0f);

    __shared__ float s_red[QBS];
    s_red[tid] = res;
    __syncthreads();
#pragma unroll
    for (int st = QBS / 2; st > 0; st >>= 1) {
        if (tid < st) s_red[tid] += s_red[tid + st];
        __syncthreads();
    }
    if (tid == 0)
        g_partial[dir * (B_ * QCHUNKS) + b * QCHUNKS + blockIdx.x] = s_red[0];
}

__global__ void __launch_bounds__(NPART)
finalize_kernel(const float* __restrict__ weights, float* __restrict__ out)
{
    const int t = threadIdx.x;                 // 0..511
    __shared__ float s[NPART];
    const int b = (t & 255) >> 4;              // index: dir*256 + b*16 + chunk
    s[t] = g_partial[t] * weights[b] * (1.0f / (16.0f * 4096.0f));
    __syncthreads();
#pragma unroll
    for (int st = NPART / 2; st > 0; st >>= 1) {
        if (t < st) s[t] += s[t + st];
        __syncthreads();
    }
    if (t == 0) out[0] = s[0];
}

extern "C" void kernel_launch(void* const* d_in, const int* in_sizes, int n_in,
                              void* d_out, int out_size)
{
    const float* src = (const float*)d_in[0];   // [16, 4096, 3]
    const float* tgt = (const float*)d_in[1];   // [16, 4096, 3]
    const float* w   = (const float*)d_in[2];   // [16]

    const int zgrid = (2 * B_ * CELLS + 1023) / 1024;      // 844
    const int pgrid = (NPTS_ALL + 1023) / 1024;            // 128

    zero_cnt_kernel<<<zgrid, 1024>>>();
    count_kernel<<<pgrid, 1024>>>(src, tgt);
    scan_kernel<<<2 * B_, 1024>>>();
    zero_cnt_kernel<<<zgrid, 1024>>>();
    scatter_kernel<<<pgrid, 1024>>>(src, tgt);
    query_kernel<<<dim3(QCHUNKS, B_, 2), QBS>>>(src, tgt);
    finalize_kernel<<<1, NPART>>>(w, (float*)d_out);
}